// round 12
// baseline (speedup 1.0000x reference)
#include <cuda_runtime.h>
#include <math_constants.h>

// Quanvolutional layer, analytically collapsed (Heisenberg picture):
// with z_q = cos(w_q) * cos(pi * x_q):
//   <Z0> = z1*...*z8,  <Z1> = z0*z1,  <Z2> = z0*z1*z2,  <Z3> = z0*z1*z2*z3
// summed over 3 channels; ev_f = W_f * S_f with the cw products hoisted.
// Output = raw reshape [94,94,4] -> out[(i*94+j)*4+f].
//
// R11: config probe — same 376 warp-tasks, but 47 blocks x 256 threads
// (8 warps/CTA) instead of 94 x 128: half the CTA dispatches, 2 warps per
// SMSP for issue interleave during the MUFU batch. Body identical to R7.

#define KH 96
#define HOUT 94

__global__ __launch_bounds__(256)
void quanv_kernel(const float* __restrict__ x,
                  const float* __restrict__ w,
                  float* __restrict__ out) {
    const int warp = threadIdx.x >> 5;
    const int lane = threadIdx.x & 31;
    const int task = blockIdx.x * 8 + warp;       // 0..375, exact (47*8=376)
    const int i = task >> 2;                      // output row 0..93
    const int g = task & 3;                       // column group
    const int j = g * 30 + lane;                  // this lane's load column
    const int jc = (j < KH) ? j : (KH - 1);       // clamp OOB lanes (g=3)

    // Issue all 9 x-loads first: memory latency starts immediately.
    float v[3][3];
#pragma unroll
    for (int c = 0; c < 3; c++) {
        const float* xc = x + c * KH * KH + i * KH + jc;
#pragma unroll
        for (int r = 0; r < 3; r++)
            v[c][r] = __ldg(xc + r * KH);
    }

    // Warp-cooperative weight cosines: one MUFU per lane, then broadcast.
    float cmine = __cosf(__ldg(w + (lane < 9 ? lane : 0)));
    float cw[9];
#pragma unroll
    for (int q = 0; q < 9; q++)
        cw[q] = __shfl_sync(0xFFFFFFFFu, cmine, q);
    float W1 = cw[0] * cw[1];
    float W2 = W1 * cw[2];
    float W3 = W2 * cw[3];
    float W0 = (cw[1] * cw[2]) * (cw[3] * cw[4]) *
               (cw[5] * cw[6]) * (cw[7] * cw[8]);

    float S0 = 0.f, S1 = 0.f, S2 = 0.f, S3 = 0.f;

#pragma unroll
    for (int c = 0; c < 3; c++) {
        float A = __cosf(CUDART_PI_F * v[c][0]);
        float B = __cosf(CUDART_PI_F * v[c][1]);
        float C = __cosf(CUDART_PI_F * v[c][2]);
        float D = B * C;
        float E = A * D;
        // 4 independent shuffles
        float A1 = __shfl_down_sync(0xFFFFFFFFu, A, 1);
        float A2 = __shfl_down_sync(0xFFFFFFFFu, A, 2);
        float E1 = __shfl_down_sync(0xFFFFFFFFu, E, 1);
        float E2 = __shfl_down_sync(0xFFFFFFFFu, E, 2);

        float t01  = A * A1;        // q0*q1
        float t012 = t01 * A2;      // q0*q1*q2
        S1 += t01;
        S2 += t012;
        S3 += t012 * B;             // q0..q3
        S0 += D * (E1 * E2);        // q1*...*q8
    }

    if (lane < 30 && j < HOUT)
        reinterpret_cast<float4*>(out)[i * HOUT + j] =
            make_float4(W0 * S0, W1 * S1, W2 * S2, W3 * S3);
}

extern "C" void kernel_launch(void* const* d_in, const int* in_sizes, int n_in,
                              void* d_out, int out_size) {
    const float* x = (const float*)d_in[0];   // [1,3,96,96]
    const float* w = (const float*)d_in[1];   // [1,9]
    float* out = (float*)d_out;               // [1,4,94,94]

    // 376 warp-tasks, 8 warps/block -> 47 blocks
    quanv_kernel<<<47, 256>>>(x, w, out);
}

// round 13
// speedup vs baseline: 1.5177x; 1.5177x over previous
#include <cuda_runtime.h>
#include <math_constants.h>

// Quanvolutional layer, analytically collapsed (Heisenberg picture).
// Propagating each measured Z_j backward through the CNOT ring gives
// Pauli-Z strings over a product state, so with z_q = cos(w_q)*cos(pi*x_q):
//   <Z0> = z1*...*z8,  <Z1> = z0*z1,  <Z2> = z0*z1*z2,  <Z3> = z0*z1*z2*z3
// summed over 3 channels; weight cosines factor out: ev_f = W_f * S_f.
// Output = raw reshape [94,94,4] -> out[(i*94+j)*4+f]  (float4 store).
//
// FINAL (R12): converged configuration — 94 blocks x 128 threads.
//  - x-loads issued first (MLP=9, latency exposed once)
//  - warp-cooperative weight cosines (1 MUFU/lane + shuffle broadcast)
//  - shuffle column dedup: lane=column, 9 data MUFU, 4 shuffles/channel
//    via D=B*C, E=A*D factorization
// Measured kernel 4.06-5.12us across runs; all pipes <1% busy — remaining
// time is launch/ramp floor, not kernel-body work.

#define KH 96
#define HOUT 94

__global__ __launch_bounds__(128)
void quanv_kernel(const float* __restrict__ x,
                  const float* __restrict__ w,
                  float* __restrict__ out) {
    const int warp = threadIdx.x >> 5;
    const int lane = threadIdx.x & 31;
    const int task = blockIdx.x * 4 + warp;       // 0..375, exact
    const int i = task >> 2;                      // output row 0..93
    const int g = task & 3;                       // column group
    const int j = g * 30 + lane;                  // this lane's load column
    const int jc = (j < KH) ? j : (KH - 1);       // clamp OOB lanes (g=3)

    // Issue all 9 x-loads first: memory latency starts immediately.
    float v[3][3];
#pragma unroll
    for (int c = 0; c < 3; c++) {
        const float* xc = x + c * KH * KH + i * KH + jc;
#pragma unroll
        for (int r = 0; r < 3; r++)
            v[c][r] = __ldg(xc + r * KH);
    }

    // Warp-cooperative weight cosines: one MUFU per lane, then broadcast.
    float cmine = __cosf(__ldg(w + (lane < 9 ? lane : 0)));
    float cw[9];
#pragma unroll
    for (int q = 0; q < 9; q++)
        cw[q] = __shfl_sync(0xFFFFFFFFu, cmine, q);
    float W1 = cw[0] * cw[1];
    float W2 = W1 * cw[2];
    float W3 = W2 * cw[3];
    float W0 = (cw[1] * cw[2]) * (cw[3] * cw[4]) *
               (cw[5] * cw[6]) * (cw[7] * cw[8]);

    float S0 = 0.f, S1 = 0.f, S2 = 0.f, S3 = 0.f;

#pragma unroll
    for (int c = 0; c < 3; c++) {
        float A = __cosf(CUDART_PI_F * v[c][0]);
        float B = __cosf(CUDART_PI_F * v[c][1]);
        float C = __cosf(CUDART_PI_F * v[c][2]);
        float D = B * C;
        float E = A * D;
        // 4 independent shuffles
        float A1 = __shfl_down_sync(0xFFFFFFFFu, A, 1);
        float A2 = __shfl_down_sync(0xFFFFFFFFu, A, 2);
        float E1 = __shfl_down_sync(0xFFFFFFFFu, E, 1);
        float E2 = __shfl_down_sync(0xFFFFFFFFu, E, 2);

        float t01  = A * A1;        // q0*q1
        float t012 = t01 * A2;      // q0*q1*q2
        S1 += t01;
        S2 += t012;
        S3 += t012 * B;             // q0..q3
        S0 += D * (E1 * E2);        // q1*...*q8
    }

    if (lane < 30 && j < HOUT)
        reinterpret_cast<float4*>(out)[i * HOUT + j] =
            make_float4(W0 * S0, W1 * S1, W2 * S2, W3 * S3);
}

extern "C" void kernel_launch(void* const* d_in, const int* in_sizes, int n_in,
                              void* d_out, int out_size) {
    const float* x = (const float*)d_in[0];   // [1,3,96,96]
    const float* w = (const float*)d_in[1];   // [1,9]
    float* out = (float*)d_out;               // [1,4,94,94]

    // 94 rows x 4 column-groups = 376 warp-tasks, 4 warps/block -> 94 blocks
    quanv_kernel<<<94, 128>>>(x, w, out);
}